// round 2
// baseline (speedup 1.0000x reference)
#include <cuda_runtime.h>
#include <cuda_fp16.h>
#include <math.h>

#define BB 64
#define TT 512
#define EMBD 128
#define HH 1024
#define FH 4096
#define NV 128
#define MR (BB*TT)   // 32768 rows

// ---------------- scratch (device globals; no allocation allowed) -------------
__device__ float  g_x[(size_t)MR*EMBD];      // 16 MB embedded input
__device__ float  g_xz[(size_t)MR*FH];       // 512 MB precomputed input GEMM
__device__ float  g_h[(size_t)MR*HH];        // 128 MB layer output (fp32, feeds next GEMM)
__device__ __half g_stateh[2*BB*HH];         // h ping-pong (fp16)
__device__ __half g_Uh[2*(size_t)FH*HH];     // fp16 U, permuted [ctaRow][k]
__device__ unsigned g_bar_count;             // grid barrier (monotonic)
__device__ volatile unsigned g_bar_phase;

// ---------------- helpers ----------------------------------------------------
__device__ __forceinline__ unsigned f2tf32(float x){
  unsigned u; asm("cvt.rna.tf32.f32 %0, %1;" : "=r"(u) : "f"(x)); return u;
}
__device__ __forceinline__ void mma8(float* d, unsigned a0,unsigned a1,unsigned a2,unsigned a3,
                                     unsigned b0,unsigned b1){
  asm volatile("mma.sync.aligned.m16n8k8.row.col.f32.tf32.tf32.f32 "
    "{%0,%1,%2,%3},{%4,%5,%6,%7},{%8,%9},{%0,%1,%2,%3};\n"
    : "+f"(d[0]),"+f"(d[1]),"+f"(d[2]),"+f"(d[3])
    : "r"(a0),"r"(a1),"r"(a2),"r"(a3),"r"(b0),"r"(b1));
}
__device__ __forceinline__ void mma16(float* d, unsigned a0,unsigned a1,unsigned a2,unsigned a3,
                                      unsigned b0,unsigned b1){
  asm volatile("mma.sync.aligned.m16n8k16.row.col.f32.f16.f16.f32 "
    "{%0,%1,%2,%3},{%4,%5,%6,%7},{%8,%9},{%0,%1,%2,%3};\n"
    : "+f"(d[0]),"+f"(d[1]),"+f"(d[2]),"+f"(d[3])
    : "r"(a0),"r"(a1),"r"(a2),"r"(a3),"r"(b0),"r"(b1));
}
__device__ __forceinline__ void cpa16(void* smem, const void* g){
  unsigned s = (unsigned)__cvta_generic_to_shared(smem);
  asm volatile("cp.async.cg.shared.global [%0],[%1],16;\n" :: "r"(s),"l"(g));
}
#define CPC() asm volatile("cp.async.commit_group;\n" ::: "memory")
#define CPW1() asm volatile("cp.async.wait_group 1;\n" ::: "memory")
#define CPW0() asm volatile("cp.async.wait_group 0;\n" ::: "memory")

__device__ __forceinline__ float sigf(float x){ return 1.f/(1.f+expf(-x)); }

__device__ __forceinline__ void grid_sync(unsigned nb, unsigned& phase){
  __threadfence();                 // all threads: drain h stores to L2
  __syncthreads();
  if(threadIdx.x==0){
    unsigned target = phase + 1u;
    unsigned arr = atomicAdd(&g_bar_count, 1u);
    if((arr % nb) == (nb-1u)) g_bar_phase = target;
    else while(g_bar_phase != target) __nanosleep(32);
    phase = target;
  }
  __syncthreads();
}

// ---------------- embedding gather -------------------------------------------
__global__ void embed_k(const int* __restrict__ tok, const float* __restrict__ emb){
  int i = blockIdx.x*blockDim.x + threadIdx.x;
  if(i < MR*EMBD){
    int r = i >> 7; int e = i & 127;
    g_x[i] = emb[tok[r]*EMBD + e];
  }
}

__global__ void zero_k(){
  int i = blockIdx.x*256 + threadIdx.x;
  if(i < 2*BB*HH) g_stateh[i] = __float2half(0.f);
}

// U [k=1024][c=4096] fp32  ->  g_Uh permuted: row R = (n>>3)*32 + q*8 + (n&7),
// (q = c>>10, n = c&1023), layout [R][k] fp16, contiguous in k.
__global__ void convU_k(const float* __restrict__ U, __half* __restrict__ Uh){
  __shared__ float tile[32][33];
  int kb = blockIdx.y*32, cb = blockIdx.x*32;
  int tx = threadIdx.x, ty = threadIdx.y;     // 32 x 8
  #pragma unroll
  for(int i=0;i<32;i+=8)
    tile[ty+i][tx] = U[(size_t)(kb+ty+i)*FH + cb+tx];
  __syncthreads();
  #pragma unroll
  for(int i=0;i<32;i+=8){
    int c = cb + ty + i;
    int n = c & 1023, q = c >> 10;
    int R = ((n>>3)<<5) + (q<<3) + (n&7);
    Uh[(size_t)R*HH + kb + tx] = __float2half(tile[tx][ty+i]);
  }
}

// ---------------- generic tf32 GEMM: C[M,N] = A[M,K]@B[K,N] + bias -----------
__global__ __launch_bounds__(256) void gemm_k(const float* __restrict__ A,
    const float* __restrict__ Bm, const float* __restrict__ bias,
    float* __restrict__ C, int K, int N){
  __shared__ unsigned sA[128][36];
  __shared__ unsigned sB[32][72];
  const int tid = threadIdx.x;
  const int warp = tid>>5, lane = tid&31, g = lane>>2, tg = lane&3;
  const int wm = warp>>1, wn = warp&1;
  const int m0 = blockIdx.y*128;
  const int n0 = blockIdx.x*64;

  float acc[2][4][4];
  #pragma unroll
  for(int a=0;a<2;a++)
    #pragma unroll
    for(int b=0;b<4;b++)
      #pragma unroll
      for(int c=0;c<4;c++) acc[a][b][c]=0.f;

  const int kt = K >> 5;
  for(int kb=0; kb<kt; kb++){
    int kofs = kb*32;
    #pragma unroll
    for(int i=0;i<16;i++){ int e=i*256+tid; int r=e>>5, c=e&31;
      sA[r][c] = f2tf32(A[(size_t)(m0+r)*K + kofs + c]); }
    #pragma unroll
    for(int i=0;i<8;i++){ int e=i*256+tid; int r=e>>6, c=e&63;
      sB[r][c] = f2tf32(Bm[(size_t)(kofs+r)*N + n0 + c]); }
    __syncthreads();
    #pragma unroll
    for(int k8=0;k8<4;k8++){
      int kk = k8*8;
      unsigned a_[2][4];
      #pragma unroll
      for(int mi=0;mi<2;mi++){
        int mr = wm*32 + mi*16;
        a_[mi][0]=sA[mr+g  ][kk+tg];   a_[mi][1]=sA[mr+8+g][kk+tg];
        a_[mi][2]=sA[mr+g  ][kk+tg+4]; a_[mi][3]=sA[mr+8+g][kk+tg+4];
      }
      #pragma unroll
      for(int ni=0;ni<4;ni++){
        int nc = wn*32 + ni*8;
        unsigned b0 = sB[kk+tg  ][nc+g];
        unsigned b1 = sB[kk+tg+4][nc+g];
        #pragma unroll
        for(int mi=0;mi<2;mi++)
          mma8(acc[mi][ni], a_[mi][0],a_[mi][1],a_[mi][2],a_[mi][3], b0,b1);
      }
    }
    __syncthreads();
  }
  #pragma unroll
  for(int mi=0;mi<2;mi++)
    #pragma unroll
    for(int ni=0;ni<4;ni++){
      int row = m0 + wm*32 + mi*16 + g;
      int col = n0 + wn*32 + ni*8 + 2*tg;
      float2 bv = *(const float2*)&bias[col];
      float2 v0 = make_float2(acc[mi][ni][0]+bv.x, acc[mi][ni][1]+bv.y);
      float2 v1 = make_float2(acc[mi][ni][2]+bv.x, acc[mi][ni][3]+bv.y);
      *(float2*)&C[(size_t)row*N + col]     = v0;
      *(float2*)&C[(size_t)(row+8)*N + col] = v1;
    }
}

// ---------------- persistent LSTM layer --------------------------------------
// 128 CTAs x 256 threads. CTA nb owns hidden cols nb*8..nb*8+7 (x 4 gates = 32
// z-cols). Per step: z = xz[:,t] + h_{t-1} @ U (fp16 MMA, cp.async double-buffered),
// gate math, c in registers, h_t (fp16) to global, out (fp32) to g_h.
__global__ __launch_bounds__(256,1) void lstm_k(const float* __restrict__ xz,
    const __half* __restrict__ Uh, float* __restrict__ out){
  __shared__ __align__(16) __half sAh[2][64][72];  // h tile 64 x 64 (+pad)
  __shared__ __align__(16) __half sBh[2][32][72];  // U tile 32 x 64 (n-major)
  __shared__ float sZ[64][36];
  const int tid  = threadIdx.x;
  const int warp = tid>>5, lane = tid&31, g = lane>>2, tg = lane&3;
  const int wm = warp>>1, wn = warp&1;            // 4 x 2 warp grid
  const int nb = blockIdx.x;
  __half* h0 = g_stateh;
  __half* h1 = g_stateh + BB*HH;
  const __half* Ub = Uh + (size_t)(nb*32)*HH;

  // per-chunk copy indices
  const int ar0 = tid>>3,        ac0 = tid&7;       // sA elems 0..255
  const int ar1 = (256+tid)>>3,  ac1 = tid&7;       // sA elems 256..511
  const int br  = tid>>3,        bc  = tid&7;       // sB elems 0..255

  float creg[2];
  creg[0]=0.f; creg[1]=0.f;
  unsigned phase = g_bar_phase;

  #pragma unroll 1
  for(int t=0;t<TT;t++){
    const __half* hr = (t&1)? h1 : h0;
    __half*       hw = (t&1)? h0 : h1;
    float acc[2][4];
    #pragma unroll
    for(int b=0;b<2;b++){ acc[b][0]=0.f; acc[b][1]=0.f; acc[b][2]=0.f; acc[b][3]=0.f; }

    // prefetch chunk 0
    {
      cpa16(&sAh[0][ar0][ac0*8], hr + ar0*HH + ac0*8);
      cpa16(&sAh[0][ar1][ac1*8], hr + ar1*HH + ac1*8);
      cpa16(&sBh[0][br ][bc *8], Ub + (size_t)br*HH + bc*8);
      CPC();
    }
    #pragma unroll 1
    for(int kb=0;kb<16;kb++){
      if(kb<15){
        int kofs=(kb+1)*64; int nbuf=(kb+1)&1;
        cpa16(&sAh[nbuf][ar0][ac0*8], hr + ar0*HH + kofs + ac0*8);
        cpa16(&sAh[nbuf][ar1][ac1*8], hr + ar1*HH + kofs + ac1*8);
        cpa16(&sBh[nbuf][br ][bc *8], Ub + (size_t)br*HH + kofs + bc*8);
        CPC(); CPW1();
      } else {
        CPW0();
      }
      __syncthreads();
      const int buf = kb&1;
      #pragma unroll
      for(int ks=0;ks<4;ks++){
        int kk = ks*16;
        int mr = wm*16;
        unsigned a0 = *(const unsigned*)&sAh[buf][mr+g  ][kk+2*tg];
        unsigned a1 = *(const unsigned*)&sAh[buf][mr+8+g][kk+2*tg];
        unsigned a2 = *(const unsigned*)&sAh[buf][mr+g  ][kk+2*tg+8];
        unsigned a3 = *(const unsigned*)&sAh[buf][mr+8+g][kk+2*tg+8];
        #pragma unroll
        for(int ni=0;ni<2;ni++){
          int nc = wn*16 + ni*8;
          unsigned b0 = *(const unsigned*)&sBh[buf][nc+g][kk+2*tg];
          unsigned b1 = *(const unsigned*)&sBh[buf][nc+g][kk+2*tg+8];
          mma16(acc[ni], a0,a1,a2,a3, b0,b1);
        }
      }
      __syncthreads();
    }
    // stage z tile (64 x 32) to smem
    #pragma unroll
    for(int ni=0;ni<2;ni++){
      int row = wm*16 + g;
      int col = wn*16 + ni*8 + 2*tg;
      sZ[row  ][col]=acc[ni][0]; sZ[row  ][col+1]=acc[ni][1];
      sZ[row+8][col]=acc[ni][2]; sZ[row+8][col+1]=acc[ni][3];
    }
    __syncthreads();
    // gate math: 64 b x 8 nn = 512 cells, 2 per thread; c stays in registers
    #pragma unroll
    for(int j=0;j<2;j++){
      int item = j*256 + tid;
      int b = item>>3, nn = item&7;
      int n = nb*8 + nn;
      size_t xrow = (size_t)(b*TT + t)*FH;
      float zi = sZ[b][nn]    + __ldg(&xz[xrow + n]);
      float zf = sZ[b][8+nn]  + __ldg(&xz[xrow + HH   + n]);
      float zg = sZ[b][16+nn] + __ldg(&xz[xrow + 2*HH + n]);
      float zo = sZ[b][24+nn] + __ldg(&xz[xrow + 3*HH + n]);
      float cn = sigf(zf)*creg[j] + sigf(zi)*tanhf(zg);
      float hn = sigf(zo)*tanhf(cn);
      creg[j] = cn;
      hw[b*HH + n] = __float2half(hn);
      out[(size_t)(b*TT + t)*HH + n] = hn;
    }
    grid_sync(128u, phase);
  }
}

// ---------------- launch ------------------------------------------------------
extern "C" void kernel_launch(void* const* d_in, const int* in_sizes, int n_in,
                              void* d_out, int out_size){
  const int*   tok = (const int*)  d_in[0];
  const float* emb = (const float*)d_in[1];
  const float* W0  = (const float*)d_in[2];
  const float* U0  = (const float*)d_in[3];
  const float* b0  = (const float*)d_in[4];
  const float* W1  = (const float*)d_in[5];
  const float* U1  = (const float*)d_in[6];
  const float* b1  = (const float*)d_in[7];
  const float* Wd  = (const float*)d_in[8];
  const float* bd  = (const float*)d_in[9];
  float* out = (float*)d_out;

  float *px, *pxz, *ph; __half *pUh;
  cudaGetSymbolAddress((void**)&px,  g_x);
  cudaGetSymbolAddress((void**)&pxz, g_xz);
  cudaGetSymbolAddress((void**)&ph,  g_h);
  cudaGetSymbolAddress((void**)&pUh, g_Uh);

  // x = emb[tokens]; U -> fp16 permuted
  embed_k<<<(MR*EMBD+255)/256, 256>>>(tok, emb);
  convU_k<<<dim3(FH/32, HH/32), dim3(32,8)>>>(U0, pUh);
  convU_k<<<dim3(FH/32, HH/32), dim3(32,8)>>>(U1, pUh + (size_t)FH*HH);
  // xz0 = x @ W0 + b0
  gemm_k<<<dim3(FH/64, MR/128), 256>>>(px, W0, b0, pxz, EMBD, FH);
  // layer 0 recurrence
  zero_k<<<(2*BB*HH+255)/256, 256>>>();
  lstm_k<<<128, 256>>>(pxz, pUh, ph);
  // xz1 = h0 @ W1 + b1
  gemm_k<<<dim3(FH/64, MR/128), 256>>>(ph, W1, b1, pxz, HH, FH);
  // layer 1 recurrence
  zero_k<<<(2*BB*HH+255)/256, 256>>>();
  lstm_k<<<128, 256>>>(pxz, pUh + (size_t)FH*HH, ph);
  // logits = h1 @ Wd + bd
  gemm_k<<<dim3(NV/64, MR/128), 256>>>(ph, Wd, bd, out, HH, NV);
}

// round 4
// speedup vs baseline: 1.2310x; 1.2310x over previous
#include <cuda_runtime.h>
#include <cuda_fp16.h>
#include <math.h>

#define BB 64
#define TT 512
#define EMBD 128
#define HH 1024
#define FH 4096
#define NV 128
#define MR (BB*TT)   // 32768 rows

// ---------------- scratch (device globals; no allocation allowed) -------------
__device__ float  g_x[(size_t)MR*EMBD];      // 16 MB embedded input
__device__ float  g_xz[(size_t)MR*FH];       // 512 MB precomputed input GEMM
__device__ float  g_h[(size_t)MR*HH];        // 128 MB layer output (fp32)
__device__ __half g_stateh[2*BB*HH];         // h ping-pong (fp16)
__device__ __half g_Uh[2*(size_t)FH*HH];     // fp16 U, permuted [R][k]
__device__ unsigned g_bar_count;             // grid barrier (monotonic)
__device__ volatile unsigned g_bar_phase;

// ---------------- helpers ----------------------------------------------------
__device__ __forceinline__ unsigned f2tf32(float x){
  unsigned u; asm("cvt.rna.tf32.f32 %0, %1;" : "=r"(u) : "f"(x)); return u;
}
__device__ __forceinline__ void mma8(float* d, unsigned a0,unsigned a1,unsigned a2,unsigned a3,
                                     unsigned b0,unsigned b1){
  asm volatile("mma.sync.aligned.m16n8k8.row.col.f32.tf32.tf32.f32 "
    "{%0,%1,%2,%3},{%4,%5,%6,%7},{%8,%9},{%0,%1,%2,%3};\n"
    : "+f"(d[0]),"+f"(d[1]),"+f"(d[2]),"+f"(d[3])
    : "r"(a0),"r"(a1),"r"(a2),"r"(a3),"r"(b0),"r"(b1));
}
__device__ __forceinline__ void mma16(float* d, unsigned a0,unsigned a1,unsigned a2,unsigned a3,
                                      unsigned b0,unsigned b1){
  asm volatile("mma.sync.aligned.m16n8k16.row.col.f32.f16.f16.f32 "
    "{%0,%1,%2,%3},{%4,%5,%6,%7},{%8,%9},{%0,%1,%2,%3};\n"
    : "+f"(d[0]),"+f"(d[1]),"+f"(d[2]),"+f"(d[3])
    : "r"(a0),"r"(a1),"r"(a2),"r"(a3),"r"(b0),"r"(b1));
}
__device__ __forceinline__ void cpa16(void* smem, const void* g){
  unsigned s = (unsigned)__cvta_generic_to_shared(smem);
  asm volatile("cp.async.cg.shared.global [%0],[%1],16;\n" :: "r"(s),"l"(g));
}
#define CPC()  asm volatile("cp.async.commit_group;\n" ::: "memory")
#define CPW2() asm volatile("cp.async.wait_group 2;\n" ::: "memory")
#define CPW1() asm volatile("cp.async.wait_group 1;\n" ::: "memory")
#define CPW0() asm volatile("cp.async.wait_group 0;\n" ::: "memory")

__device__ __forceinline__ float sigf(float x){
  return __fdividef(1.f, 1.f + __expf(-x));
}
__device__ __forceinline__ float tanhfast(float x){
  return __fdividef(2.f, 1.f + __expf(-2.f*x)) - 1.f;
}

__device__ __forceinline__ void grid_sync(unsigned nb, unsigned& phase){
  __syncthreads();
  if(threadIdx.x==0){
    unsigned target = phase + 1u;
    __threadfence();
    unsigned arr = atomicAdd(&g_bar_count, 1u);
    if((arr % nb) == (nb-1u)) g_bar_phase = target;
    else while(g_bar_phase != target) __nanosleep(32);
    __threadfence();
    phase = target;
  }
  __syncthreads();
}

// ---------------- small kernels ----------------------------------------------
__global__ void embed_k(const int* __restrict__ tok, const float* __restrict__ emb){
  int i = blockIdx.x*blockDim.x + threadIdx.x;
  if(i < MR*EMBD){
    int r = i >> 7; int e = i & 127;
    g_x[i] = emb[tok[r]*EMBD + e];
  }
}
__global__ void zero_k(){
  int i = blockIdx.x*256 + threadIdx.x;
  if(i < 2*BB*HH) g_stateh[i] = __float2half(0.f);
}
// U [k][c] fp32 -> g_Uh rows R=(n>>3)*32+q*8+(n&7), layout [R][k] fp16
__global__ void convU_k(const float* __restrict__ U, __half* __restrict__ Uh){
  __shared__ float tile[32][33];
  int kb = blockIdx.y*32, cb = blockIdx.x*32;
  int tx = threadIdx.x, ty = threadIdx.y;
  #pragma unroll
  for(int i=0;i<32;i+=8)
    tile[ty+i][tx] = U[(size_t)(kb+ty+i)*FH + cb+tx];
  __syncthreads();
  #pragma unroll
  for(int i=0;i<32;i+=8){
    int c = cb + ty + i;
    int n = c & 1023, q = c >> 10;
    int R = ((n>>3)<<5) + (q<<3) + (n&7);
    Uh[(size_t)R*HH + kb + tx] = __float2half(tile[tx][ty+i]);
  }
}

// ---------------- generic tf32 GEMM ------------------------------------------
__global__ __launch_bounds__(256) void gemm_k(const float* __restrict__ A,
    const float* __restrict__ Bm, const float* __restrict__ bias,
    float* __restrict__ C, int K, int N){
  __shared__ unsigned sA[128][36];
  __shared__ unsigned sB[32][72];
  const int tid = threadIdx.x;
  const int warp = tid>>5, lane = tid&31, g = lane>>2, tg = lane&3;
  const int wm = warp>>1, wn = warp&1;
  const int m0 = blockIdx.y*128;
  const int n0 = blockIdx.x*64;
  float acc[2][4][4];
  #pragma unroll
  for(int a=0;a<2;a++)
    #pragma unroll
    for(int b=0;b<4;b++)
      #pragma unroll
      for(int c=0;c<4;c++) acc[a][b][c]=0.f;
  const int kt = K >> 5;
  for(int kb=0; kb<kt; kb++){
    int kofs = kb*32;
    #pragma unroll
    for(int i=0;i<16;i++){ int e=i*256+tid; int r=e>>5, c=e&31;
      sA[r][c] = f2tf32(A[(size_t)(m0+r)*K + kofs + c]); }
    #pragma unroll
    for(int i=0;i<8;i++){ int e=i*256+tid; int r=e>>6, c=e&63;
      sB[r][c] = f2tf32(Bm[(size_t)(kofs+r)*N + n0 + c]); }
    __syncthreads();
    #pragma unroll
    for(int k8=0;k8<4;k8++){
      int kk = k8*8;
      unsigned a_[2][4];
      #pragma unroll
      for(int mi=0;mi<2;mi++){
        int mr = wm*32 + mi*16;
        a_[mi][0]=sA[mr+g  ][kk+tg];   a_[mi][1]=sA[mr+8+g][kk+tg];
        a_[mi][2]=sA[mr+g  ][kk+tg+4]; a_[mi][3]=sA[mr+8+g][kk+tg+4];
      }
      #pragma unroll
      for(int ni=0;ni<4;ni++){
        int nc = wn*32 + ni*8;
        unsigned b0 = sB[kk+tg  ][nc+g];
        unsigned b1 = sB[kk+tg+4][nc+g];
        #pragma unroll
        for(int mi=0;mi<2;mi++)
          mma8(acc[mi][ni], a_[mi][0],a_[mi][1],a_[mi][2],a_[mi][3], b0,b1);
      }
    }
    __syncthreads();
  }
  #pragma unroll
  for(int mi=0;mi<2;mi++)
    #pragma unroll
    for(int ni=0;ni<4;ni++){
      int row = m0 + wm*32 + mi*16 + g;
      int col = n0 + wn*32 + ni*8 + 2*tg;
      float2 bv = *(const float2*)&bias[col];
      float2 v0 = make_float2(acc[mi][ni][0]+bv.x, acc[mi][ni][1]+bv.y);
      float2 v1 = make_float2(acc[mi][ni][2]+bv.x, acc[mi][ni][3]+bv.y);
      *(float2*)&C[(size_t)row*N + col]     = v0;
      *(float2*)&C[(size_t)(row+8)*N + col] = v1;
    }
}

// ---------------- persistent LSTM layer --------------------------------------
// 128 CTAs x 256 threads, ~125 KB dynamic smem:
//   sU   : U slice (32 z-cols x 1024 k) fp16, resident all 512 steps
//   sA   : 4-stage cp.async ring of h chunks (64 x 64 fp16)
//   sXZ  : xz ping-pong (prefetched one step ahead)
//   sZ   : z staging for gate math
#define UPITCH 1032
#define SM_U   (32*UPITCH*2)              // 66048
#define SM_A   (4*64*72*2)                // 36864
#define SM_XZ  (2*64*32*4)                // 16384
#define SM_Z   (64*36*4)                  // 9216
#define SMEM_LSTM (SM_U + SM_A + SM_XZ + SM_Z)

__global__ __launch_bounds__(256,1) void lstm_k(const float* __restrict__ xz,
    const __half* __restrict__ Uh, float* __restrict__ out){
  extern __shared__ __align__(16) char smem[];
  __half* sU = (__half*)smem;
  __half (*sA)[64][72]  = (__half(*)[64][72])(smem + SM_U);
  float (*sXZ)[64][32]  = (float(*)[64][32])(smem + SM_U + SM_A);
  float (*sZ)[36]       = (float(*)[36])(smem + SM_U + SM_A + SM_XZ);

  const int tid  = threadIdx.x;
  const int warp = tid>>5, lane = tid&31, g = lane>>2, tg = lane&3;
  const int wm = warp>>1, wn = warp&1;            // 4 x 2 warps
  const int nb = blockIdx.x;
  __half* h0 = g_stateh;
  __half* h1 = g_stateh + BB*HH;
  const __half* Ub = Uh + (size_t)(nb*32)*HH;

  // ---- load U slice into smem (once) + xz for t=0 ----
  #pragma unroll
  for(int i=0;i<16;i++){
    int idx = i*256 + tid;            // 4096 x 16B
    int r = idx>>7, c16 = idx&127;
    cpa16(&sU[r*UPITCH + c16*8], Ub + (size_t)r*HH + c16*8);
  }
  CPC();
  {
    #pragma unroll
    for(int i=0;i<2;i++){
      int c = i*256 + tid;            // 512 x 16B
      int b = c>>3, rest = c&7, q = rest>>1, hf = rest&1;
      cpa16(&sXZ[0][b][q*8 + hf*4],
            xz + (size_t)(b*TT)*FH + q*HH + nb*8 + hf*4);
    }
    CPC();
  }

  float creg[2]; creg[0]=0.f; creg[1]=0.f;
  unsigned phase = g_bar_phase;

  #pragma unroll 1
  for(int t=0;t<TT;t++){
    const __half* hr = (t&1)? h1 : h0;
    __half*       hw = (t&1)? h0 : h1;
    const int tb = t&1;

    // ---- per-step prologue: stages 0..2 (+ next-step xz in stage-2 group) ----
    #pragma unroll
    for(int s=0;s<3;s++){
      int kofs = s*64;
      #pragma unroll
      for(int i=0;i<2;i++){
        int c = i*256 + tid;          // 512 x 16B per stage
        int r = c>>3, cc = c&7;
        cpa16(&sA[s][r][cc*8], hr + r*HH + kofs + cc*8);
      }
      if(s==2 && t+1<TT){
        #pragma unroll
        for(int i=0;i<2;i++){
          int c = i*256 + tid;
          int b = c>>3, rest = c&7, q = rest>>1, hf = rest&1;
          cpa16(&sXZ[tb^1][b][q*8 + hf*4],
                xz + (size_t)(b*TT + t+1)*FH + q*HH + nb*8 + hf*4);
        }
      }
      CPC();
    }

    float acc[2][4];
    #pragma unroll
    for(int b=0;b<2;b++){ acc[b][0]=0.f; acc[b][1]=0.f; acc[b][2]=0.f; acc[b][3]=0.f; }

    #pragma unroll 1
    for(int kb=0;kb<16;kb++){
      if(kb<=13) CPW2(); else if(kb==14) CPW1(); else CPW0();
      __syncthreads();
      if(kb+3<16){
        int kofs = (kb+3)*64, s = (kb+3)&3;
        #pragma unroll
        for(int i=0;i<2;i++){
          int c = i*256 + tid;
          int r = c>>3, cc = c&7;
          cpa16(&sA[s][r][cc*8], hr + r*HH + kofs + cc*8);
        }
        CPC();
      }
      const int buf = kb&3;
      #pragma unroll
      for(int ks=0;ks<4;ks++){
        int kk = ks*16;
        int mr = wm*16;
        unsigned a0 = *(const unsigned*)&sA[buf][mr+g  ][kk+2*tg];
        unsigned a1 = *(const unsigned*)&sA[buf][mr+8+g][kk+2*tg];
        unsigned a2 = *(const unsigned*)&sA[buf][mr+g  ][kk+2*tg+8];
        unsigned a3 = *(const unsigned*)&sA[buf][mr+8+g][kk+2*tg+8];
        int kgl = kb*64 + kk;
        #pragma unroll
        for(int ni=0;ni<2;ni++){
          int nr = wn*16 + ni*8 + g;
          unsigned b0 = *(const unsigned*)&sU[nr*UPITCH + kgl + 2*tg];
          unsigned b1 = *(const unsigned*)&sU[nr*UPITCH + kgl + 2*tg + 8];
          mma16(acc[ni], a0,a1,a2,a3, b0,b1);
        }
      }
    }
    // ---- stage z (64 x 32) ----
    #pragma unroll
    for(int ni=0;ni<2;ni++){
      int row = wm*16 + g;
      int col = wn*16 + ni*8 + 2*tg;
      sZ[row  ][col]=acc[ni][0]; sZ[row  ][col+1]=acc[ni][1];
      sZ[row+8][col]=acc[ni][2]; sZ[row+8][col+1]=acc[ni][3];
    }
    __syncthreads();
    // ---- gate math: 2 cells per thread, c in registers ----
    #pragma unroll
    for(int j=0;j<2;j++){
      int item = j*256 + tid;
      int b = item>>3, nn = item&7;
      int n = nb*8 + nn;
      float zi = sZ[b][nn]    + sXZ[tb][b][nn];
      float zf = sZ[b][8+nn]  + sXZ[tb][b][8+nn];
      float zg = sZ[b][16+nn] + sXZ[tb][b][16+nn];
      float zo = sZ[b][24+nn] + sXZ[tb][b][24+nn];
      float cn = sigf(zf)*creg[j] + sigf(zi)*tanhfast(zg);
      float hn = sigf(zo)*tanhfast(cn);
      creg[j] = cn;
      hw[b*HH + n] = __float2half(hn);
      out[(size_t)(b*TT + t)*HH + n] = hn;
    }
    if(t+1<TT) grid_sync(128u, phase);
  }
}

// ---------------- launch ------------------------------------------------------
extern "C" void kernel_launch(void* const* d_in, const int* in_sizes, int n_in,
                              void* d_out, int out_size){
  const int*   tok = (const int*)  d_in[0];
  const float* emb = (const float*)d_in[1];
  const float* W0  = (const float*)d_in[2];
  const float* U0  = (const float*)d_in[3];
  const float* b0  = (const float*)d_in[4];
  const float* W1  = (const float*)d_in[5];
  const float* U1  = (const float*)d_in[6];
  const float* b1  = (const float*)d_in[7];
  const float* Wd  = (const float*)d_in[8];
  const float* bd  = (const float*)d_in[9];
  float* out = (float*)d_out;

  float *px, *pxz, *ph; __half *pUh;
  cudaGetSymbolAddress((void**)&px,  g_x);
  cudaGetSymbolAddress((void**)&pxz, g_xz);
  cudaGetSymbolAddress((void**)&ph,  g_h);
  cudaGetSymbolAddress((void**)&pUh, g_Uh);

  cudaFuncSetAttribute(lstm_k, cudaFuncAttributeMaxDynamicSharedMemorySize, SMEM_LSTM);

  embed_k<<<(MR*EMBD+255)/256, 256>>>(tok, emb);
  convU_k<<<dim3(FH/32, HH/32), dim3(32,8)>>>(U0, pUh);
  convU_k<<<dim3(FH/32, HH/32), dim3(32,8)>>>(U1, pUh + (size_t)FH*HH);
  gemm_k<<<dim3(FH/64, MR/128), 256>>>(px, W0, b0, pxz, EMBD, FH);
  zero_k<<<(2*BB*HH+255)/256, 256>>>();
  lstm_k<<<128, 256, SMEM_LSTM>>>(pxz, pUh, ph);
  gemm_k<<<dim3(FH/64, MR/128), 256>>>(ph, W1, b1, pxz, HH, FH);
  zero_k<<<(2*BB*HH+255)/256, 256>>>();
  lstm_k<<<128, 256, SMEM_LSTM>>>(pxz, pUh + (size_t)FH*HH, ph);
  gemm_k<<<dim3(NV/64, MR/128), 256>>>(ph, Wd, bd, out, HH, NV);
}

// round 5
// speedup vs baseline: 1.3117x; 1.0655x over previous
#include <cuda_runtime.h>
#include <cuda_fp16.h>
#include <math.h>

#define BB 64
#define TT 512
#define EMBD 128
#define HH 1024
#define FH 4096
#define NV 128
#define MR (BB*TT)   // 32768 rows

// ---------------- scratch (device globals; no allocation allowed) -------------
__device__ float  g_x[(size_t)MR*EMBD];      // 16 MB embedded input
__device__ float  g_xz[(size_t)MR*FH];       // 512 MB precomputed input GEMM
__device__ float  g_h[(size_t)MR*HH];        // 128 MB layer output (fp32)
__device__ __half g_stateh[2*BB*HH];         // h ping-pong (fp16)
__device__ __half g_Uh[2*(size_t)FH*HH];     // fp16 U, permuted [R][k]
__device__ unsigned g_bar_count;             // grid barrier (monotonic)
__device__ volatile unsigned g_bar_phase;

// ---------------- helpers ----------------------------------------------------
__device__ __forceinline__ unsigned f2tf32(float x){
  unsigned u; asm("cvt.rna.tf32.f32 %0, %1;" : "=r"(u) : "f"(x)); return u;
}
__device__ __forceinline__ void mma8(float* d, unsigned a0,unsigned a1,unsigned a2,unsigned a3,
                                     unsigned b0,unsigned b1){
  asm volatile("mma.sync.aligned.m16n8k8.row.col.f32.tf32.tf32.f32 "
    "{%0,%1,%2,%3},{%4,%5,%6,%7},{%8,%9},{%0,%1,%2,%3};\n"
    : "+f"(d[0]),"+f"(d[1]),"+f"(d[2]),"+f"(d[3])
    : "r"(a0),"r"(a1),"r"(a2),"r"(a3),"r"(b0),"r"(b1));
}
__device__ __forceinline__ void mma16(float* d, unsigned a0,unsigned a1,unsigned a2,unsigned a3,
                                      unsigned b0,unsigned b1){
  asm volatile("mma.sync.aligned.m16n8k16.row.col.f32.f16.f16.f32 "
    "{%0,%1,%2,%3},{%4,%5,%6,%7},{%8,%9},{%0,%1,%2,%3};\n"
    : "+f"(d[0]),"+f"(d[1]),"+f"(d[2]),"+f"(d[3])
    : "r"(a0),"r"(a1),"r"(a2),"r"(a3),"r"(b0),"r"(b1));
}
__device__ __forceinline__ void ldsm4(unsigned& r0, unsigned& r1, unsigned& r2, unsigned& r3,
                                      unsigned addr){
  asm volatile("ldmatrix.sync.aligned.m8n8.x4.shared.b16 {%0,%1,%2,%3}, [%4];"
    : "=r"(r0),"=r"(r1),"=r"(r2),"=r"(r3) : "r"(addr));
}
__device__ __forceinline__ void cpa16(void* smem, const void* g){
  unsigned s = (unsigned)__cvta_generic_to_shared(smem);
  asm volatile("cp.async.cg.shared.global [%0],[%1],16;\n" :: "r"(s),"l"(g));
}
#define CPC()  asm volatile("cp.async.commit_group;\n" ::: "memory")
#define CPW2() asm volatile("cp.async.wait_group 2;\n" ::: "memory")
#define CPW1() asm volatile("cp.async.wait_group 1;\n" ::: "memory")
#define CPW0() asm volatile("cp.async.wait_group 0;\n" ::: "memory")

__device__ __forceinline__ float sigf(float x){
  return __fdividef(1.f, 1.f + __expf(-x));
}
__device__ __forceinline__ float tanhfast(float x){
  return __fdividef(2.f, 1.f + __expf(-2.f*x)) - 1.f;
}

__device__ __forceinline__ void grid_sync(unsigned nb, unsigned& phase){
  __syncthreads();
  if(threadIdx.x==0){
    unsigned target = phase + 1u;
    __threadfence();
    unsigned arr = atomicAdd(&g_bar_count, 1u);
    if((arr % nb) == (nb-1u)) g_bar_phase = target;
    else while(g_bar_phase != target) __nanosleep(16);
    __threadfence();
    phase = target;
  }
  __syncthreads();
}

// ---------------- small kernels ----------------------------------------------
__global__ void embed_k(const int* __restrict__ tok, const float* __restrict__ emb){
  int i = blockIdx.x*blockDim.x + threadIdx.x;
  if(i < MR*EMBD){
    int r = i >> 7; int e = i & 127;
    g_x[i] = emb[tok[r]*EMBD + e];
  }
}
__global__ void zero_k(){
  int i = blockIdx.x*256 + threadIdx.x;
  if(i < 2*BB*HH) g_stateh[i] = __float2half(0.f);
}
// U [k][c] fp32 -> g_Uh rows R=(n>>3)*32+q*8+(n&7), layout [R][k] fp16
__global__ void convU_k(const float* __restrict__ U, __half* __restrict__ Uh){
  __shared__ float tile[32][33];
  int kb = blockIdx.y*32, cb = blockIdx.x*32;
  int tx = threadIdx.x, ty = threadIdx.y;
  #pragma unroll
  for(int i=0;i<32;i+=8)
    tile[ty+i][tx] = U[(size_t)(kb+ty+i)*FH + cb+tx];
  __syncthreads();
  #pragma unroll
  for(int i=0;i<32;i+=8){
    int c = cb + ty + i;
    int n = c & 1023, q = c >> 10;
    int R = ((n>>3)<<5) + (q<<3) + (n&7);
    Uh[(size_t)R*HH + kb + tx] = __float2half(tile[tx][ty+i]);
  }
}

// ---------------- generic tf32 GEMM ------------------------------------------
__global__ __launch_bounds__(256) void gemm_k(const float* __restrict__ A,
    const float* __restrict__ Bm, const float* __restrict__ bias,
    float* __restrict__ C, int K, int N){
  __shared__ unsigned sA[128][36];
  __shared__ unsigned sB[32][72];
  const int tid = threadIdx.x;
  const int warp = tid>>5, lane = tid&31, g = lane>>2, tg = lane&3;
  const int wm = warp>>1, wn = warp&1;
  const int m0 = blockIdx.y*128;
  const int n0 = blockIdx.x*64;
  float acc[2][4][4];
  #pragma unroll
  for(int a=0;a<2;a++)
    #pragma unroll
    for(int b=0;b<4;b++)
      #pragma unroll
      for(int c=0;c<4;c++) acc[a][b][c]=0.f;
  const int kt = K >> 5;
  for(int kb=0; kb<kt; kb++){
    int kofs = kb*32;
    #pragma unroll
    for(int i=0;i<16;i++){ int e=i*256+tid; int r=e>>5, c=e&31;
      sA[r][c] = f2tf32(A[(size_t)(m0+r)*K + kofs + c]); }
    #pragma unroll
    for(int i=0;i<8;i++){ int e=i*256+tid; int r=e>>6, c=e&63;
      sB[r][c] = f2tf32(Bm[(size_t)(kofs+r)*N + n0 + c]); }
    __syncthreads();
    #pragma unroll
    for(int k8=0;k8<4;k8++){
      int kk = k8*8;
      unsigned a_[2][4];
      #pragma unroll
      for(int mi=0;mi<2;mi++){
        int mr = wm*32 + mi*16;
        a_[mi][0]=sA[mr+g  ][kk+tg];   a_[mi][1]=sA[mr+8+g][kk+tg];
        a_[mi][2]=sA[mr+g  ][kk+tg+4]; a_[mi][3]=sA[mr+8+g][kk+tg+4];
      }
      #pragma unroll
      for(int ni=0;ni<4;ni++){
        int nc = wn*32 + ni*8;
        unsigned b0 = sB[kk+tg  ][nc+g];
        unsigned b1 = sB[kk+tg+4][nc+g];
        #pragma unroll
        for(int mi=0;mi<2;mi++)
          mma8(acc[mi][ni], a_[mi][0],a_[mi][1],a_[mi][2],a_[mi][3], b0,b1);
      }
    }
    __syncthreads();
  }
  #pragma unroll
  for(int mi=0;mi<2;mi++)
    #pragma unroll
    for(int ni=0;ni<4;ni++){
      int row = m0 + wm*32 + mi*16 + g;
      int col = n0 + wn*32 + ni*8 + 2*tg;
      float2 bv = *(const float2*)&bias[col];
      float2 v0 = make_float2(acc[mi][ni][0]+bv.x, acc[mi][ni][1]+bv.y);
      float2 v1 = make_float2(acc[mi][ni][2]+bv.x, acc[mi][ni][3]+bv.y);
      *(float2*)&C[(size_t)row*N + col]     = v0;
      *(float2*)&C[(size_t)(row+8)*N + col] = v1;
    }
}

// ---------------- persistent LSTM layer --------------------------------------
// 128 CTAs x 256 threads, ~141.5 KB dynamic smem:
//   sU : U slice (32 z-cols x 1024 k) fp16, resident all 512 steps
//   sA : 4-stage cp.async ring of h chunks (64 rows x 128 k fp16, 17408 B/stage)
//   sZ : z staging for gate math
// Per step: 8 chunks (BK=128), ldmatrix fragments, xz via direct LDG regs.
#define UPITCH   1032                 // halves; 2064 B row pitch (16B-rotated banks)
#define APITCHH  136                  // halves; 272 B row pitch
#define ASTAGE_B (64*272)             // 17408 B per stage
#define SM_U   (32*UPITCH*2)          // 66048
#define SM_A   (4*ASTAGE_B)           // 69632
#define SM_Z   (64*36*4)              // 9216
#define SMEM_LSTM (SM_U + SM_A + SM_Z)

__global__ __launch_bounds__(256,1) void lstm_k(const float* __restrict__ xz,
    const __half* __restrict__ Uh, float* __restrict__ out){
  extern __shared__ __align__(16) char smem[];
  __half* sU = (__half*)smem;
  __half* sAh = (__half*)(smem + SM_U);
  float (*sZ)[36] = (float(*)[36])(smem + SM_U + SM_A);

  const int tid  = threadIdx.x;
  const int warp = tid>>5, lane = tid&31, g = lane>>2, tg = lane&3;
  const int wm = warp>>1, wn = warp&1;            // 4 x 2 warps (m16 x n16 tiles)
  const int nb = blockIdx.x;
  __half* h0 = g_stateh;
  __half* h1 = g_stateh + BB*HH;
  const __half* Ub = Uh + (size_t)(nb*32)*HH;

  // per-lane ldmatrix base addresses
  const unsigned suBase = (unsigned)__cvta_generic_to_shared(sU);
  const unsigned saBase = (unsigned)__cvta_generic_to_shared(sAh);
  const unsigned aOff = (unsigned)((wm*16 + (lane&7) + ((lane>>3)&1)*8)*272 + (lane>>4)*16);
  const unsigned bOff = (unsigned)((wn*16 + (lane&7) + ((lane>>4)&1)*8)*2064 + ((lane>>3)&1)*16);

  // gate-math cell indices (2 cells per thread)
  const int b0i = tid>>3,        nn0 = tid&7;
  const int b1i = (256+tid)>>3,  nn1 = tid&7;

  // ---- load U slice into smem (once) ----
  #pragma unroll
  for(int i=0;i<16;i++){
    int idx = i*256 + tid;            // 4096 x 16B
    int r = idx>>7, c16 = idx&127;
    cpa16(&sU[r*UPITCH + c16*8], Ub + (size_t)r*HH + c16*8);
  }
  CPC();

  float creg[2]; creg[0]=0.f; creg[1]=0.f;
  unsigned phase = g_bar_phase;

  #pragma unroll 1
  for(int t=0;t<TT;t++){
    const __half* hr = (t&1)? h1 : h0;
    __half*       hw = (t&1)? h0 : h1;

    // ---- xz gate inputs: issue LDGs now, consume at step tail ----
    float xzv[2][4];
    {
      size_t r0 = (size_t)(b0i*TT + t)*FH + nb*8 + nn0;
      size_t r1 = (size_t)(b1i*TT + t)*FH + nb*8 + nn1;
      xzv[0][0]=__ldg(&xz[r0]);        xzv[0][1]=__ldg(&xz[r0+HH]);
      xzv[0][2]=__ldg(&xz[r0+2*HH]);   xzv[0][3]=__ldg(&xz[r0+3*HH]);
      xzv[1][0]=__ldg(&xz[r1]);        xzv[1][1]=__ldg(&xz[r1+HH]);
      xzv[1][2]=__ldg(&xz[r1+2*HH]);   xzv[1][3]=__ldg(&xz[r1+3*HH]);
    }

    // ---- prologue: issue h stages 0..2 ----
    #pragma unroll
    for(int s=0;s<3;s++){
      int kofs = s*128;
      #pragma unroll
      for(int i=0;i<4;i++){
        int idx = i*256 + tid;        // 1024 x 16B per stage
        int r = idx>>4, c16 = idx&15;
        cpa16(sAh + s*(ASTAGE_B/2) + r*APITCHH + c16*8,
              hr + r*HH + kofs + c16*8);
      }
      CPC();
    }

    float acc[2][4];
    #pragma unroll
    for(int b=0;b<2;b++){ acc[b][0]=0.f; acc[b][1]=0.f; acc[b][2]=0.f; acc[b][3]=0.f; }

    #pragma unroll 1
    for(int kb=0;kb<8;kb++){
      if(kb<=5) CPW2(); else if(kb==6) CPW1(); else CPW0();
      __syncthreads();
      if(kb+3<8){
        int kofs = (kb+3)*128, s = (kb+3)&3;
        #pragma unroll
        for(int i=0;i<4;i++){
          int idx = i*256 + tid;
          int r = idx>>4, c16 = idx&15;
          cpa16(sAh + s*(ASTAGE_B/2) + r*APITCHH + c16*8,
                hr + r*HH + kofs + c16*8);
        }
        CPC();
      }
      const unsigned aS = saBase + aOff + (unsigned)(kb&3)*ASTAGE_B;
      const unsigned bS = suBase + bOff + (unsigned)kb*256u;
      #pragma unroll
      for(int ks=0;ks<8;ks++){
        unsigned a0,a1,a2,a3, bb0,bb1,bb2,bb3;
        ldsm4(a0,a1,a2,a3, aS + ks*32u);
        ldsm4(bb0,bb1,bb2,bb3, bS + ks*32u);
        mma16(acc[0], a0,a1,a2,a3, bb0,bb1);
        mma16(acc[1], a0,a1,a2,a3, bb2,bb3);
      }
    }
    // ---- stage z (64 x 32) ----
    #pragma unroll
    for(int ni=0;ni<2;ni++){
      int row = wm*16 + g;
      int col = wn*16 + ni*8 + 2*tg;
      sZ[row  ][col]=acc[ni][0]; sZ[row  ][col+1]=acc[ni][1];
      sZ[row+8][col]=acc[ni][2]; sZ[row+8][col+1]=acc[ni][3];
    }
    __syncthreads();
    // ---- gate math: 2 cells per thread, c in registers ----
    {
      float zi = sZ[b0i][nn0]    + xzv[0][0];
      float zf = sZ[b0i][8+nn0]  + xzv[0][1];
      float zg = sZ[b0i][16+nn0] + xzv[0][2];
      float zo = sZ[b0i][24+nn0] + xzv[0][3];
      float cn = sigf(zf)*creg[0] + sigf(zi)*tanhfast(zg);
      float hn = sigf(zo)*tanhfast(cn);
      creg[0] = cn;
      hw[b0i*HH + nb*8 + nn0] = __float2half(hn);
      out[(size_t)(b0i*TT + t)*HH + nb*8 + nn0] = hn;
    }
    {
      float zi = sZ[b1i][nn1]    + xzv[1][0];
      float zf = sZ[b1i][8+nn1]  + xzv[1][1];
      float zg = sZ[b1i][16+nn1] + xzv[1][2];
      float zo = sZ[b1i][24+nn1] + xzv[1][3];
      float cn = sigf(zf)*creg[1] + sigf(zi)*tanhfast(zg);
      float hn = sigf(zo)*tanhfast(cn);
      creg[1] = cn;
      hw[b1i*HH + nb*8 + nn1] = __float2half(hn);
      out[(size_t)(b1i*TT + t)*HH + nb*8 + nn1] = hn;
    }
    if(t+1<TT) grid_sync(128u, phase);
  }
}

// ---------------- launch ------------------------------------------------------
extern "C" void kernel_launch(void* const* d_in, const int* in_sizes, int n_in,
                              void* d_out, int out_size){
  const int*   tok = (const int*)  d_in[0];
  const float* emb = (const float*)d_in[1];
  const float* W0  = (const float*)d_in[2];
  const float* U0  = (const float*)d_in[3];
  const float* b0  = (const float*)d_in[4];
  const float* W1  = (const float*)d_in[5];
  const float* U1  = (const float*)d_in[6];
  const float* b1  = (const float*)d_in[7];
  const float* Wd  = (const float*)d_in[8];
  const float* bd  = (const float*)d_in[9];
  float* out = (float*)d_out;

  float *px, *pxz, *ph; __half *pUh;
  cudaGetSymbolAddress((void**)&px,  g_x);
  cudaGetSymbolAddress((void**)&pxz, g_xz);
  cudaGetSymbolAddress((void**)&ph,  g_h);
  cudaGetSymbolAddress((void**)&pUh, g_Uh);

  cudaFuncSetAttribute(lstm_k, cudaFuncAttributeMaxDynamicSharedMemorySize, SMEM_LSTM);

  embed_k<<<(MR*EMBD+255)/256, 256>>>(tok, emb);
  convU_k<<<dim3(FH/32, HH/32), dim3(32,8)>>>(U0, pUh);
  convU_k<<<dim3(FH/32, HH/32), dim3(32,8)>>>(U1, pUh + (size_t)FH*HH);
  gemm_k<<<dim3(FH/64, MR/128), 256>>>(px, W0, b0, pxz, EMBD, FH);
  zero_k<<<(2*BB*HH+255)/256, 256>>>();
  lstm_k<<<128, 256, SMEM_LSTM>>>(pxz, pUh, ph);
  gemm_k<<<dim3(FH/64, MR/128), 256>>>(ph, W1, b1, pxz, HH, FH);
  zero_k<<<(2*BB*HH+255)/256, 256>>>();
  lstm_k<<<128, 256, SMEM_LSTM>>>(pxz, pUh + (size_t)FH*HH, ph);
  gemm_k<<<dim3(NV/64, MR/128), 256>>>(ph, Wd, bd, out, HH, NV);
}